// round 1
// baseline (speedup 1.0000x reference)
#include <cuda_runtime.h>

// ---------------- scratch (no cudaMalloc allowed) ----------------
__device__ float g_M[128 * 128];                 // W_main @ W_ref^T
__device__ float g_A[4 * 128 * 128 * 128];       // main @ M

// ---------------- Kernel 0: M = W_main @ W_ref^T ----------------
__global__ void wprod_kernel(const float* __restrict__ Wm,
                             const float* __restrict__ Wr) {
    __shared__ float wm[128];
    int c = blockIdx.x;
    int t = threadIdx.x;
    wm[t] = Wm[c * 128 + t];
    __syncthreads();
    const float* wr = Wr + t * 128;
    float s = 0.f;
#pragma unroll 8
    for (int d = 0; d < 128; d++) s += wm[d] * wr[d];
    g_M[c * 128 + t] = s;
}

// ---------------- Kernel 1: A = main @ M  (65536x128 @ 128x128) ----------------
__global__ void __launch_bounds__(256) gemm_kernel(const float* __restrict__ X) {
    __shared__ float Xs[16][128];   // transposed tile: Xs[k][row]
    __shared__ float Ms[16][128];   // Ms[k][col]
    const int tid = threadIdx.x;
    const int tx = tid & 15;
    const int ty = tid >> 4;
    const int row0 = blockIdx.x * 128;

    float acc[8][8];
#pragma unroll
    for (int i = 0; i < 8; i++)
#pragma unroll
        for (int j = 0; j < 8; j++) acc[i][j] = 0.f;

    const int lr = tid >> 2;            // 0..63
    const int lk = (tid & 3) * 4;       // 0,4,8,12
    const int mr = tid >> 5;            // 0..7
    const int mc = (tid & 31) * 4;      // 0..124

    for (int k0 = 0; k0 < 128; k0 += 16) {
        float4 xa = *(const float4*)&X[(row0 + lr) * 128 + k0 + lk];
        float4 xb = *(const float4*)&X[(row0 + lr + 64) * 128 + k0 + lk];
        Xs[lk + 0][lr] = xa.x; Xs[lk + 1][lr] = xa.y;
        Xs[lk + 2][lr] = xa.z; Xs[lk + 3][lr] = xa.w;
        Xs[lk + 0][lr + 64] = xb.x; Xs[lk + 1][lr + 64] = xb.y;
        Xs[lk + 2][lr + 64] = xb.z; Xs[lk + 3][lr + 64] = xb.w;
        *(float4*)&Ms[mr][mc]     = *(const float4*)&g_M[(k0 + mr) * 128 + mc];
        *(float4*)&Ms[mr + 8][mc] = *(const float4*)&g_M[(k0 + mr + 8) * 128 + mc];
        __syncthreads();
#pragma unroll
        for (int k = 0; k < 16; k++) {
            float4 a0 = *(const float4*)&Xs[k][ty * 4];
            float4 a1 = *(const float4*)&Xs[k][64 + ty * 4];
            float4 b0 = *(const float4*)&Ms[k][tx * 4];
            float4 b1 = *(const float4*)&Ms[k][64 + tx * 4];
            float a[8] = {a0.x, a0.y, a0.z, a0.w, a1.x, a1.y, a1.z, a1.w};
            float b[8] = {b0.x, b0.y, b0.z, b0.w, b1.x, b1.y, b1.z, b1.w};
#pragma unroll
            for (int i = 0; i < 8; i++)
#pragma unroll
                for (int j = 0; j < 8; j++) acc[i][j] += a[i] * b[j];
        }
        __syncthreads();
    }
#pragma unroll
    for (int i = 0; i < 8; i++) {
        int row = row0 + ((i < 4) ? (ty * 4 + i) : (64 + ty * 4 + i - 4));
        float4 v0 = make_float4(acc[i][0], acc[i][1], acc[i][2], acc[i][3]);
        float4 v1 = make_float4(acc[i][4], acc[i][5], acc[i][6], acc[i][7]);
        *(float4*)&g_A[row * 128 + tx * 4] = v0;
        *(float4*)&g_A[row * 128 + 64 + tx * 4] = v1;
    }
}

// ---------------- Kernel 2: local 5x5 attention ----------------
// Tile 8x8 pixels, halo 12x12. 4 threads per pixel (32 channels each).
// Smem layouts with skewed part-offsets => conflict-free scalar LDS:
//   sRef / sA : word = pix*161 + part*40 + c   (bank = pix + 8*part + c  mod 32)
//   sV        : word = pix*89  + part*24 + i   (bank = pix*25 + 24*part + i mod 32, injective)
#define SREF 161
#define SA   161
#define SV   89
#define SMEM_FLOATS (144 * SREF + 64 * SA + 144 * SV)

__global__ void __launch_bounds__(256, 1) attn_kernel(const float* __restrict__ ref,
                                                      const float* __restrict__ refv,
                                                      float* __restrict__ out) {
    extern __shared__ float smem[];
    float* sRef = smem;                  // 144 * 161
    float* sA   = sRef + 144 * SREF;     // 64 * 161
    float* sV   = sA + 64 * SA;          // 144 * 89

    const int b = blockIdx.z;
    const int ty0 = blockIdx.y * 8;
    const int tx0 = blockIdx.x * 8;
    const int tid = threadIdx.x;

    // ---- load ref halo (zero padded) ----
    for (int t = tid; t < 144 * 32; t += 256) {
        int hp = t >> 5, c4 = t & 31;
        int gy = ty0 - 2 + hp / 12;
        int gx = tx0 - 2 + hp % 12;
        float4 v = make_float4(0.f, 0.f, 0.f, 0.f);
        if ((unsigned)gy < 128u && (unsigned)gx < 128u)
            v = *(const float4*)&ref[(((b * 128 + gy) * 128) + gx) * 128 + (c4 << 2)];
        int base = hp * SREF + (c4 >> 3) * 40 + ((c4 & 7) << 2);
        sRef[base] = v.x; sRef[base + 1] = v.y; sRef[base + 2] = v.z; sRef[base + 3] = v.w;
    }
    // ---- load query tile A ----
    for (int t = tid; t < 64 * 32; t += 256) {
        int p = t >> 5, c4 = t & 31;
        int gy = ty0 + (p >> 3);
        int gx = tx0 + (p & 7);
        float4 v = *(const float4*)&g_A[(((b * 128 + gy) * 128) + gx) * 128 + (c4 << 2)];
        int base = p * SA + (c4 >> 3) * 40 + ((c4 & 7) << 2);
        sA[base] = v.x; sA[base + 1] = v.y; sA[base + 2] = v.z; sA[base + 3] = v.w;
    }
    // ---- load value halo (zero padded) ----
    for (int t = tid; t < 144 * 16; t += 256) {
        int hp = t >> 4, c4 = t & 15;
        int gy = ty0 - 2 + hp / 12;
        int gx = tx0 - 2 + hp % 12;
        float4 v = make_float4(0.f, 0.f, 0.f, 0.f);
        if ((unsigned)gy < 128u && (unsigned)gx < 128u)
            v = *(const float4*)&refv[(((b * 128 + gy) * 128) + gx) * 64 + (c4 << 2)];
        int base = hp * SV + (c4 >> 2) * 24 + ((c4 & 3) << 2);
        sV[base] = v.x; sV[base + 1] = v.y; sV[base + 2] = v.z; sV[base + 3] = v.w;
    }
    __syncthreads();

    const int pixel = tid >> 2;
    const int part  = tid & 3;
    const int py = pixel >> 3;
    const int px = pixel & 7;

    const float* qp = &sA[pixel * SA + part * 40];
    const float* kp[25];
#pragma unroll
    for (int dy = 0; dy < 5; dy++)
#pragma unroll
        for (int dx = 0; dx < 5; dx++)
            kp[dy * 5 + dx] = &sRef[((py + dy) * 12 + (px + dx)) * SREF + part * 40];

    float acc[25];
#pragma unroll
    for (int n = 0; n < 25; n++) acc[n] = 0.f;

#pragma unroll
    for (int cc = 0; cc < 32; cc++) {
        float qv = qp[cc];
#pragma unroll
        for (int n = 0; n < 25; n++) acc[n] += qv * kp[n][cc];
    }

    // reduce the 4 channel-parts (lanes tid^1, tid^2 are the same pixel)
#pragma unroll
    for (int n = 0; n < 25; n++) {
        float v = acc[n];
        v += __shfl_xor_sync(0xffffffffu, v, 1);
        v += __shfl_xor_sync(0xffffffffu, v, 2);
        acc[n] = v;
    }

    // softmax over 25 (computed redundantly in all 4 part-lanes)
    float m = acc[0];
#pragma unroll
    for (int n = 1; n < 25; n++) m = fmaxf(m, acc[n]);
    float s = 0.f;
#pragma unroll
    for (int n = 0; n < 25; n++) { acc[n] = expf(acc[n] - m); s += acc[n]; }
    float inv = 1.f / s;

    // weighted sum of values: this part handles bins [part*16, part*16+16)
    float oacc[16];
#pragma unroll
    for (int i = 0; i < 16; i++) oacc[i] = 0.f;
#pragma unroll
    for (int dy = 0; dy < 5; dy++)
#pragma unroll
        for (int dx = 0; dx < 5; dx++) {
            int n = dy * 5 + dx;
            const float* vp = &sV[((py + dy) * 12 + (px + dx)) * SV + part * 24];
            float w = acc[n];
#pragma unroll
            for (int i = 0; i < 16; i++) oacc[i] += w * vp[i];
        }

    const int gy = ty0 + py;
    const int gx = tx0 + px;
    float* op = &out[(((b * 128 + gy) * 128) + gx) * 64 + part * 16];
#pragma unroll
    for (int i = 0; i < 16; i += 4) {
        float4 v = make_float4(oacc[i] * inv, oacc[i + 1] * inv,
                               oacc[i + 2] * inv, oacc[i + 3] * inv);
        *(float4*)&op[i] = v;
    }
}

// ---------------- launch ----------------
extern "C" void kernel_launch(void* const* d_in, const int* in_sizes, int n_in,
                              void* d_out, int out_size) {
    const float* main_ = (const float*)d_in[0];
    const float* ref   = (const float*)d_in[1];
    const float* refv  = (const float*)d_in[2];
    const float* Wm    = (const float*)d_in[3];
    const float* Wr    = (const float*)d_in[4];
    float* out = (float*)d_out;

    const size_t smem_bytes = SMEM_FLOATS * sizeof(float);  // 185216
    cudaFuncSetAttribute(attn_kernel, cudaFuncAttributeMaxDynamicSharedMemorySize,
                         (int)smem_bytes);

    wprod_kernel<<<128, 128>>>(Wm, Wr);
    gemm_kernel<<<512, 256>>>(main_);
    attn_kernel<<<dim3(16, 16, 4), 256, smem_bytes>>>(ref, refv, out);
}

// round 2
// speedup vs baseline: 1.0605x; 1.0605x over previous
#include <cuda_runtime.h>

typedef unsigned long long ull;

// ---------------- scratch (no cudaMalloc allowed) ----------------
__device__ float g_M[128 * 128];                 // W_main @ W_ref^T
__device__ float g_A[4 * 128 * 128 * 128];       // main @ M

// ---------------- packed fp32x2 helpers ----------------
__device__ __forceinline__ ull pk2(float lo, float hi) {
    ull r; asm("mov.b64 %0, {%1,%2};" : "=l"(r) : "f"(lo), "f"(hi)); return r;
}
__device__ __forceinline__ void upk2(ull v, float& lo, float& hi) {
    asm("mov.b64 {%0,%1}, %2;" : "=f"(lo), "=f"(hi) : "l"(v));
}
__device__ __forceinline__ ull fma2(ull a, ull b, ull c) {
    ull d; asm("fma.rn.f32x2 %0, %1, %2, %3;" : "=l"(d) : "l"(a), "l"(b), "l"(c));
    return d;
}
__device__ __forceinline__ ull d2l(double v) { return __double_as_longlong(v); }

// ---------------- Kernel 0: M = W_main @ W_ref^T ----------------
__global__ void __launch_bounds__(128) wprod_kernel(const float* __restrict__ Wm,
                                                    const float* __restrict__ Wr) {
    __shared__ float wm[128];
    const int c = blockIdx.x;
    const int t = threadIdx.x;
    wm[t] = Wm[c * 128 + t];
    __syncthreads();
    const float4* wr = (const float4*)(Wr + t * 128);
    float s0 = 0.f, s1 = 0.f, s2 = 0.f, s3 = 0.f;
#pragma unroll
    for (int d = 0; d < 32; d += 4) {
        float4 v0 = wr[d + 0], v1 = wr[d + 1], v2 = wr[d + 2], v3 = wr[d + 3];
        s0 += wm[4*d+ 0]*v0.x + wm[4*d+ 1]*v0.y + wm[4*d+ 2]*v0.z + wm[4*d+ 3]*v0.w;
        s1 += wm[4*d+ 4]*v1.x + wm[4*d+ 5]*v1.y + wm[4*d+ 6]*v1.z + wm[4*d+ 7]*v1.w;
        s2 += wm[4*d+ 8]*v2.x + wm[4*d+ 9]*v2.y + wm[4*d+10]*v2.z + wm[4*d+11]*v2.w;
        s3 += wm[4*d+12]*v3.x + wm[4*d+13]*v3.y + wm[4*d+14]*v3.z + wm[4*d+15]*v3.w;
    }
    g_M[c * 128 + t] = (s0 + s1) + (s2 + s3);
}

// ---------------- Kernel 1: A = main @ M  (65536x128 @ 128x128), FFMA2 ----------------
__global__ void __launch_bounds__(256) gemm_kernel(const float* __restrict__ X) {
    __shared__ float Xs[16][128];   // transposed: Xs[k][row]
    __shared__ float Ms[16][128];   // Ms[k][col]
    const int tid = threadIdx.x;
    const int tx = tid & 15;
    const int ty = tid >> 4;
    const int row0 = blockIdx.x * 128;

    ull acc[4][8];
#pragma unroll
    for (int p = 0; p < 4; p++)
#pragma unroll
        for (int j = 0; j < 8; j++) acc[p][j] = 0ull;

    const int lr = tid >> 2;            // 0..63
    const int lk = (tid & 3) * 4;       // 0,4,8,12
    const int mr = tid >> 5;            // 0..7
    const int mc = (tid & 31) * 4;      // 0..124

    for (int k0 = 0; k0 < 128; k0 += 16) {
        float4 xa = *(const float4*)&X[(row0 + lr) * 128 + k0 + lk];
        float4 xb = *(const float4*)&X[(row0 + lr + 64) * 128 + k0 + lk];
        Xs[lk + 0][lr] = xa.x; Xs[lk + 1][lr] = xa.y;
        Xs[lk + 2][lr] = xa.z; Xs[lk + 3][lr] = xa.w;
        Xs[lk + 0][lr + 64] = xb.x; Xs[lk + 1][lr + 64] = xb.y;
        Xs[lk + 2][lr + 64] = xb.z; Xs[lk + 3][lr + 64] = xb.w;
        *(float4*)&Ms[mr][mc]     = *(const float4*)&g_M[(k0 + mr) * 128 + mc];
        *(float4*)&Ms[mr + 8][mc] = *(const float4*)&g_M[(k0 + mr + 8) * 128 + mc];
        __syncthreads();
#pragma unroll
        for (int k = 0; k < 16; k++) {
            double2 a0 = *(const double2*)&Xs[k][ty * 4];        // rows pairs
            double2 a1 = *(const double2*)&Xs[k][64 + ty * 4];
            float4 b0 = *(const float4*)&Ms[k][tx * 4];
            float4 b1 = *(const float4*)&Ms[k][64 + tx * 4];
            ull ap[4] = {d2l(a0.x), d2l(a0.y), d2l(a1.x), d2l(a1.y)};
            ull bp[8] = {pk2(b0.x, b0.x), pk2(b0.y, b0.y), pk2(b0.z, b0.z), pk2(b0.w, b0.w),
                         pk2(b1.x, b1.x), pk2(b1.y, b1.y), pk2(b1.z, b1.z), pk2(b1.w, b1.w)};
#pragma unroll
            for (int p = 0; p < 4; p++)
#pragma unroll
                for (int j = 0; j < 8; j++) acc[p][j] = fma2(ap[p], bp[j], acc[p][j]);
        }
        __syncthreads();
    }
    // epilogue: pair p -> rows r0,r1 ; lane lo -> r0, hi -> r1
    const int rbase[4] = {ty * 4, ty * 4 + 2, 64 + ty * 4, 64 + ty * 4 + 2};
#pragma unroll
    for (int p = 0; p < 4; p++) {
        float lo[8], hi[8];
#pragma unroll
        for (int j = 0; j < 8; j++) upk2(acc[p][j], lo[j], hi[j]);
        const int r0 = row0 + rbase[p];
        *(float4*)&g_A[r0 * 128 + tx * 4]            = make_float4(lo[0], lo[1], lo[2], lo[3]);
        *(float4*)&g_A[r0 * 128 + 64 + tx * 4]       = make_float4(lo[4], lo[5], lo[6], lo[7]);
        *(float4*)&g_A[(r0 + 1) * 128 + tx * 4]      = make_float4(hi[0], hi[1], hi[2], hi[3]);
        *(float4*)&g_A[(r0 + 1) * 128 + 64 + tx * 4] = make_float4(hi[4], hi[5], hi[6], hi[7]);
    }
}

// ---------------- Kernel 2: local 5x5 attention (vectorized) ----------------
// 8x8 pixel tile, 12x12 halo, 4 threads/pixel (32 ch each).
// Layouts (floats), all 16B-aligned rows, LDS.128 conflict-free:
//   sRef/sA: word = pix*164 + part*40 + c   (16B-bank: px + 2*part, distinct per phase)
//   sV     : word = pix*100 + part*24 + i   (16B-bank: px + 6*part, distinct per phase)
#define SREF 164
#define SA   164
#define SV   100
#define SMEM_FLOATS (144 * SREF + 64 * SA + 144 * SV)

__global__ void __launch_bounds__(256, 1) attn_kernel(const float* __restrict__ ref,
                                                      const float* __restrict__ refv,
                                                      float* __restrict__ out) {
    extern __shared__ float smem[];
    float* sRef = smem;                  // 144 * 164
    float* sA   = sRef + 144 * SREF;     // 64 * 164
    float* sV   = sA + 64 * SA;          // 144 * 100

    const int b = blockIdx.z;
    const int ty0 = blockIdx.y * 8;
    const int tx0 = blockIdx.x * 8;
    const int tid = threadIdx.x;

    // ---- load ref halo (zero padded) ----
    for (int t = tid; t < 144 * 32; t += 256) {
        int hp = t >> 5, c4 = t & 31;
        int gy = ty0 - 2 + hp / 12;
        int gx = tx0 - 2 + hp % 12;
        float4 v = make_float4(0.f, 0.f, 0.f, 0.f);
        if ((unsigned)gy < 128u && (unsigned)gx < 128u)
            v = *(const float4*)&ref[(((b * 128 + gy) * 128) + gx) * 128 + (c4 << 2)];
        *(float4*)&sRef[hp * SREF + (c4 >> 3) * 40 + ((c4 & 7) << 2)] = v;
    }
    // ---- load query tile A ----
    for (int t = tid; t < 64 * 32; t += 256) {
        int p = t >> 5, c4 = t & 31;
        int gy = ty0 + (p >> 3);
        int gx = tx0 + (p & 7);
        float4 v = *(const float4*)&g_A[(((b * 128 + gy) * 128) + gx) * 128 + (c4 << 2)];
        *(float4*)&sA[p * SA + (c4 >> 3) * 40 + ((c4 & 7) << 2)] = v;
    }
    // ---- load value halo (zero padded) ----
    for (int t = tid; t < 144 * 16; t += 256) {
        int hp = t >> 4, c4 = t & 15;
        int gy = ty0 - 2 + hp / 12;
        int gx = tx0 - 2 + hp % 12;
        float4 v = make_float4(0.f, 0.f, 0.f, 0.f);
        if ((unsigned)gy < 128u && (unsigned)gx < 128u)
            v = *(const float4*)&refv[(((b * 128 + gy) * 128) + gx) * 64 + (c4 << 2)];
        *(float4*)&sV[hp * SV + (c4 >> 2) * 24 + ((c4 & 3) << 2)] = v;
    }
    __syncthreads();

    const int pixel = tid >> 2;
    const int part  = tid & 3;
    const int py = pixel >> 3;
    const int px = pixel & 7;

    // preload Q (32 channels) as 16 packed f32x2
    ull q[16];
    {
        const double2* qp = (const double2*)&sA[pixel * SA + part * 40];
#pragma unroll
        for (int m = 0; m < 8; m++) {
            double2 d = qp[m];
            q[2 * m]     = d2l(d.x);
            q[2 * m + 1] = d2l(d.y);
        }
    }

    const float* kbase = &sRef[((py * 12) + px) * SREF + part * 40];

    ull acc2[25];
#pragma unroll
    for (int n = 0; n < 25; n++) acc2[n] = 0ull;

#pragma unroll
    for (int m = 0; m < 8; m++) {
        ull q0 = q[2 * m], q1 = q[2 * m + 1];
#pragma unroll
        for (int dy = 0; dy < 5; dy++)
#pragma unroll
            for (int dx = 0; dx < 5; dx++) {
                const int n = dy * 5 + dx;
                double2 kv = *(const double2*)(kbase + (dy * 12 + dx) * SREF + 4 * m);
                acc2[n] = fma2(q0, d2l(kv.x), acc2[n]);
                acc2[n] = fma2(q1, d2l(kv.y), acc2[n]);
            }
    }

    // horizontal: pair-sum, then reduce the 4 channel-parts via shfl
    float logit[25];
#pragma unroll
    for (int n = 0; n < 25; n++) {
        float lo, hi; upk2(acc2[n], lo, hi);
        float v = lo + hi;
        v += __shfl_xor_sync(0xffffffffu, v, 1);
        v += __shfl_xor_sync(0xffffffffu, v, 2);
        logit[n] = v;
    }

    // softmax over 25 (redundant in the 4 part-lanes)
    float mx = logit[0];
#pragma unroll
    for (int n = 1; n < 25; n++) mx = fmaxf(mx, logit[n]);
    float s = 0.f;
#pragma unroll
    for (int n = 0; n < 25; n++) { logit[n] = __expf(logit[n] - mx); s += logit[n]; }
    const float inv = 1.f / s;

    // weighted value sum: this part handles bins [part*16, part*16+16)
    ull o2[8];
#pragma unroll
    for (int i = 0; i < 8; i++) o2[i] = 0ull;
    const float* vbase = &sV[((py * 12) + px) * SV + part * 24];
#pragma unroll
    for (int dy = 0; dy < 5; dy++)
#pragma unroll
        for (int dx = 0; dx < 5; dx++) {
            const int n = dy * 5 + dx;
            const ull w2 = pk2(logit[n], logit[n]);
            const double2* vp = (const double2*)(vbase + (dy * 12 + dx) * SV);
#pragma unroll
            for (int m = 0; m < 4; m++) {
                double2 v = vp[m];
                o2[2 * m]     = fma2(w2, d2l(v.x), o2[2 * m]);
                o2[2 * m + 1] = fma2(w2, d2l(v.y), o2[2 * m + 1]);
            }
        }

    const int gy = ty0 + py;
    const int gx = tx0 + px;
    float* op = &out[(((b * 128 + gy) * 128) + gx) * 64 + part * 16];
#pragma unroll
    for (int i = 0; i < 4; i++) {
        float a0, a1, a2, a3;
        upk2(o2[2 * i], a0, a1);
        upk2(o2[2 * i + 1], a2, a3);
        *(float4*)&op[4 * i] = make_float4(a0 * inv, a1 * inv, a2 * inv, a3 * inv);
    }
}

// ---------------- launch ----------------
extern "C" void kernel_launch(void* const* d_in, const int* in_sizes, int n_in,
                              void* d_out, int out_size) {
    const float* main_ = (const float*)d_in[0];
    const float* ref   = (const float*)d_in[1];
    const float* refv  = (const float*)d_in[2];
    const float* Wm    = (const float*)d_in[3];
    const float* Wr    = (const float*)d_in[4];
    float* out = (float*)d_out;

    const size_t smem_bytes = SMEM_FLOATS * sizeof(float);  // 194048
    cudaFuncSetAttribute(attn_kernel, cudaFuncAttributeMaxDynamicSharedMemorySize,
                         (int)smem_bytes);

    wprod_kernel<<<128, 128>>>(Wm, Wr);
    gemm_kernel<<<512, 256>>>(main_);
    attn_kernel<<<dim3(16, 16, 4), 256, smem_bytes>>>(ref, refv, out);
}

// round 3
// speedup vs baseline: 1.3765x; 1.2980x over previous
#include <cuda_runtime.h>

typedef unsigned long long ull;

// ---------------- scratch (no cudaMalloc allowed) ----------------
__device__ float g_M[128 * 128];                 // W_main @ W_ref^T
__device__ float g_A[4 * 128 * 128 * 128];       // main @ M
__device__ int   g_dummy[32];

// ---------------- packed fp32x2 helpers ----------------
__device__ __forceinline__ ull pk2(float lo, float hi) {
    ull r; asm("mov.b64 %0, {%1,%2};" : "=l"(r) : "f"(lo), "f"(hi)); return r;
}
__device__ __forceinline__ void upk2(ull v, float& lo, float& hi) {
    asm("mov.b64 {%0,%1}, %2;" : "=f"(lo), "=f"(hi) : "l"(v));
}
__device__ __forceinline__ ull fma2(ull a, ull b, ull c) {
    ull d; asm("fma.rn.f32x2 %0, %1, %2, %3;" : "=l"(d) : "l"(a), "l"(b), "l"(c));
    return d;
}
__device__ __forceinline__ ull d2l(double v) { return __double_as_longlong(v); }

// ---------------- Kernel 0: M = W_main @ W_ref^T ----------------
__global__ void __launch_bounds__(128) wprod_kernel(const float* __restrict__ Wm,
                                                    const float* __restrict__ Wr) {
    __shared__ float wm[128];
    const int c = blockIdx.x;
    const int t = threadIdx.x;
    wm[t] = Wm[c * 128 + t];
    __syncthreads();
    const float4* wr = (const float4*)(Wr + t * 128);
    float s0 = 0.f, s1 = 0.f, s2 = 0.f, s3 = 0.f;
#pragma unroll
    for (int d = 0; d < 32; d += 4) {
        float4 v0 = wr[d + 0], v1 = wr[d + 1], v2 = wr[d + 2], v3 = wr[d + 3];
        s0 += wm[4*d+ 0]*v0.x + wm[4*d+ 1]*v0.y + wm[4*d+ 2]*v0.z + wm[4*d+ 3]*v0.w;
        s1 += wm[4*d+ 4]*v1.x + wm[4*d+ 5]*v1.y + wm[4*d+ 6]*v1.z + wm[4*d+ 7]*v1.w;
        s2 += wm[4*d+ 8]*v2.x + wm[4*d+ 9]*v2.y + wm[4*d+10]*v2.z + wm[4*d+11]*v2.w;
        s3 += wm[4*d+12]*v3.x + wm[4*d+13]*v3.y + wm[4*d+14]*v3.z + wm[4*d+15]*v3.w;
    }
    g_M[c * 128 + t] = (s0 + s1) + (s2 + s3);
}

// ---------------- Kernel 1: A = main @ M  (65536x128 @ 128x128), FFMA2 ----------------
__global__ void __launch_bounds__(256) gemm_kernel(const float* __restrict__ X) {
    __shared__ float Xs[16][128];   // transposed: Xs[k][row]
    __shared__ float Ms[16][128];   // Ms[k][col]
    const int tid = threadIdx.x;
    const int tx = tid & 15;
    const int ty = tid >> 4;
    const int row0 = blockIdx.x * 128;

    ull acc[4][8];
#pragma unroll
    for (int p = 0; p < 4; p++)
#pragma unroll
        for (int j = 0; j < 8; j++) acc[p][j] = 0ull;

    const int lr = tid >> 2;
    const int lk = (tid & 3) * 4;
    const int mr = tid >> 5;
    const int mc = (tid & 31) * 4;

    for (int k0 = 0; k0 < 128; k0 += 16) {
        float4 xa = *(const float4*)&X[(row0 + lr) * 128 + k0 + lk];
        float4 xb = *(const float4*)&X[(row0 + lr + 64) * 128 + k0 + lk];
        Xs[lk + 0][lr] = xa.x; Xs[lk + 1][lr] = xa.y;
        Xs[lk + 2][lr] = xa.z; Xs[lk + 3][lr] = xa.w;
        Xs[lk + 0][lr + 64] = xb.x; Xs[lk + 1][lr + 64] = xb.y;
        Xs[lk + 2][lr + 64] = xb.z; Xs[lk + 3][lr + 64] = xb.w;
        *(float4*)&Ms[mr][mc]     = *(const float4*)&g_M[(k0 + mr) * 128 + mc];
        *(float4*)&Ms[mr + 8][mc] = *(const float4*)&g_M[(k0 + mr + 8) * 128 + mc];
        __syncthreads();
#pragma unroll
        for (int k = 0; k < 16; k++) {
            double2 a0 = *(const double2*)&Xs[k][ty * 4];
            double2 a1 = *(const double2*)&Xs[k][64 + ty * 4];
            float4 b0 = *(const float4*)&Ms[k][tx * 4];
            float4 b1 = *(const float4*)&Ms[k][64 + tx * 4];
            ull ap[4] = {d2l(a0.x), d2l(a0.y), d2l(a1.x), d2l(a1.y)};
            ull bp[8] = {pk2(b0.x, b0.x), pk2(b0.y, b0.y), pk2(b0.z, b0.z), pk2(b0.w, b0.w),
                         pk2(b1.x, b1.x), pk2(b1.y, b1.y), pk2(b1.z, b1.z), pk2(b1.w, b1.w)};
#pragma unroll
            for (int p = 0; p < 4; p++)
#pragma unroll
                for (int j = 0; j < 8; j++) acc[p][j] = fma2(ap[p], bp[j], acc[p][j]);
        }
        __syncthreads();
    }
    const int rbase[4] = {ty * 4, ty * 4 + 2, 64 + ty * 4, 64 + ty * 4 + 2};
#pragma unroll
    for (int p = 0; p < 4; p++) {
        float lo[8], hi[8];
#pragma unroll
        for (int j = 0; j < 8; j++) upk2(acc[p][j], lo[j], hi[j]);
        const int r0 = row0 + rbase[p];
        *(float4*)&g_A[r0 * 128 + tx * 4]            = make_float4(lo[0], lo[1], lo[2], lo[3]);
        *(float4*)&g_A[r0 * 128 + 64 + tx * 4]       = make_float4(lo[4], lo[5], lo[6], lo[7]);
        *(float4*)&g_A[(r0 + 1) * 128 + tx * 4]      = make_float4(hi[0], hi[1], hi[2], hi[3]);
        *(float4*)&g_A[(r0 + 1) * 128 + 64 + tx * 4] = make_float4(hi[4], hi[5], hi[6], hi[7]);
    }
}

// ---------------- Kernel 2: local 5x5 attention, occ-2, XOR-swizzled smem ----------
// 8x8 pixel tile, 12x12 halo, 4 threads/pixel (32 ch each). Q lives in registers.
// sRef: 144 rows x 128 floats (32 granules of 16B). store granule g at
//       g' = g ^ 2*(g>>3 low bits into [2:1]) ^ (row&1)  -> per-phase banks distinct.
// sV:   144 rows x 64 floats (16 granules). g' = g ^ ((g>>3)&1) ^ ((row&1)<<1).
#define SREF_W 128
#define SV_W   64
#define SMEM_FLOATS (144 * SREF_W + 144 * SV_W)   // 27648 floats = 110592 B

__global__ void __launch_bounds__(256, 2) attn_kernel(const float* __restrict__ ref,
                                                      const float* __restrict__ refv,
                                                      float* __restrict__ out) {
    extern __shared__ float smem[];
    float* sRef = smem;                    // 144 * 128
    float* sV   = sRef + 144 * SREF_W;     // 144 * 64

    const int b = blockIdx.z;
    const int ty0 = blockIdx.y * 8;
    const int tx0 = blockIdx.x * 8;
    const int tid = threadIdx.x;

    const int pixel = tid >> 2;
    const int part  = tid & 3;
    const int py = pixel >> 3;
    const int px = pixel & 7;

    // ---- Q: straight from g_A into packed registers ----
    ull q[16];
    {
        const float4* qp = (const float4*)&g_A[(((b * 128 + ty0 + py) * 128) + tx0 + px) * 128 + part * 32];
#pragma unroll
        for (int m = 0; m < 8; m++) {
            float4 v = qp[m];
            q[2 * m]     = pk2(v.x, v.y);
            q[2 * m + 1] = pk2(v.z, v.w);
        }
    }

    // ---- load ref halo (zero padded), swizzled ----
    for (int t = tid; t < 144 * 32; t += 256) {
        int hp = t >> 5, g = t & 31;
        int gy = ty0 - 2 + hp / 12;
        int gx = tx0 - 2 + hp % 12;
        float4 v = make_float4(0.f, 0.f, 0.f, 0.f);
        if ((unsigned)gy < 128u && (unsigned)gx < 128u)
            v = *(const float4*)&ref[(((b * 128 + gy) * 128) + gx) * 128 + (g << 2)];
        int gp = g ^ (((g >> 3) << 1) & 6) ^ (hp & 1);
        *(float4*)&sRef[hp * SREF_W + (gp << 2)] = v;
    }
    // ---- load value halo (zero padded), swizzled ----
    for (int t = tid; t < 144 * 16; t += 256) {
        int hp = t >> 4, g = t & 15;
        int gy = ty0 - 2 + hp / 12;
        int gx = tx0 - 2 + hp % 12;
        float4 v = make_float4(0.f, 0.f, 0.f, 0.f);
        if ((unsigned)gy < 128u && (unsigned)gx < 128u)
            v = *(const float4*)&refv[(((b * 128 + gy) * 128) + gx) * 64 + (g << 2)];
        int gp = g ^ ((g >> 3) & 1) ^ ((hp & 1) << 1);
        *(float4*)&sV[hp * SV_W + (gp << 2)] = v;
    }
    __syncthreads();

    // ---- logits ----
    ull acc2[25];
#pragma unroll
    for (int n = 0; n < 25; n++) acc2[n] = 0ull;

    const int rowbase = py * 12 + px;
    const int p8 = part << 3;          // granule base for this part
    const int p2 = part << 1;          // swizzle component

#pragma unroll
    for (int dy = 0; dy < 5; dy++)
#pragma unroll
        for (int dx = 0; dx < 5; dx++) {
            const int n = dy * 5 + dx;
            const int row = rowbase + dy * 12 + dx;
            const int c = p2 ^ (row & 1);              // XOR into m
            const float* kr = &sRef[row * SREF_W];
            ull a = acc2[n];
#pragma unroll
            for (int m = 0; m < 8; m++) {
                float4 kv = *(const float4*)&kr[(p8 + (m ^ c)) << 2];
                a = fma2(q[2 * m],     pk2(kv.x, kv.y), a);
                a = fma2(q[2 * m + 1], pk2(kv.z, kv.w), a);
            }
            acc2[n] = a;
        }

    // horizontal: pair-sum, then reduce the 4 channel-parts via shfl
    float logit[25];
#pragma unroll
    for (int n = 0; n < 25; n++) {
        float lo, hi; upk2(acc2[n], lo, hi);
        float v = lo + hi;
        v += __shfl_xor_sync(0xffffffffu, v, 1);
        v += __shfl_xor_sync(0xffffffffu, v, 2);
        logit[n] = v;
    }

    // softmax over 25 (redundant in the 4 part-lanes)
    float mx = logit[0];
#pragma unroll
    for (int n = 1; n < 25; n++) mx = fmaxf(mx, logit[n]);
    float s = 0.f;
#pragma unroll
    for (int n = 0; n < 25; n++) { logit[n] = __expf(logit[n] - mx); s += logit[n]; }
    const float inv = 1.f / s;

    // ---- weighted value sum: bins [part*16, part*16+16) ----
    ull o2[8];
#pragma unroll
    for (int i = 0; i < 8; i++) o2[i] = 0ull;
    const int vp4 = part << 2;
    const int vc0 = part >> 1;
#pragma unroll
    for (int dy = 0; dy < 5; dy++)
#pragma unroll
        for (int dx = 0; dx < 5; dx++) {
            const int n = dy * 5 + dx;
            const int row = rowbase + dy * 12 + dx;
            const int c = vc0 ^ ((row & 1) << 1);
            const float* vr = &sV[row * SV_W];
            const ull w2 = pk2(logit[n], logit[n]);
#pragma unroll
            for (int m = 0; m < 4; m++) {
                float4 v = *(const float4*)&vr[(vp4 + (m ^ c)) << 2];
                o2[2 * m]     = fma2(w2, pk2(v.x, v.y), o2[2 * m]);
                o2[2 * m + 1] = fma2(w2, pk2(v.z, v.w), o2[2 * m + 1]);
            }
        }

    const int gy = ty0 + py;
    const int gx = tx0 + px;
    float* op = &out[(((b * 128 + gy) * 128) + gx) * 64 + part * 16];
#pragma unroll
    for (int i = 0; i < 4; i++) {
        float a0, a1, a2, a3;
        upk2(o2[2 * i], a0, a1);
        upk2(o2[2 * i + 1], a2, a3);
        *(float4*)&op[4 * i] = make_float4(a0 * inv, a1 * inv, a2 * inv, a3 * inv);
    }
}

// ---------------- Kernel 3: tiny alignment dummy (shifts ncu window to attn) ----
__global__ void dummy_kernel() {
    if (threadIdx.x < 32) g_dummy[threadIdx.x] = (int)threadIdx.x;
}

// ---------------- launch ----------------
extern "C" void kernel_launch(void* const* d_in, const int* in_sizes, int n_in,
                              void* d_out, int out_size) {
    const float* main_ = (const float*)d_in[0];
    const float* ref   = (const float*)d_in[1];
    const float* refv  = (const float*)d_in[2];
    const float* Wm    = (const float*)d_in[3];
    const float* Wr    = (const float*)d_in[4];
    float* out = (float*)d_out;

    const size_t smem_bytes = SMEM_FLOATS * sizeof(float);  // 110592
    cudaFuncSetAttribute(attn_kernel, cudaFuncAttributeMaxDynamicSharedMemorySize,
                         (int)smem_bytes);

    wprod_kernel<<<128, 128>>>(Wm, Wr);
    gemm_kernel<<<512, 256>>>(main_);
    attn_kernel<<<dim3(16, 16, 4), 256, smem_bytes>>>(ref, refv, out);
    dummy_kernel<<<1, 32>>>();   // keeps ncu's skip-window landing on attn_kernel
}

// round 7
// speedup vs baseline: 1.4493x; 1.0529x over previous
#include <cuda_runtime.h>

typedef unsigned long long ull;

// ---------------- scratch (no cudaMalloc allowed) ----------------
__device__ float g_M[128 * 128];                 // W_main @ W_ref^T
__device__ float g_A[4 * 128 * 128 * 128];       // main @ M
__device__ int   g_dummy[32];

// ---------------- packed fp32x2 helpers ----------------
__device__ __forceinline__ ull pk2(float lo, float hi) {
    ull r; asm("mov.b64 %0, {%1,%2};" : "=l"(r) : "f"(lo), "f"(hi)); return r;
}
__device__ __forceinline__ void upk2(ull v, float& lo, float& hi) {
    asm("mov.b64 {%0,%1}, %2;" : "=f"(lo), "=f"(hi) : "l"(v));
}
__device__ __forceinline__ ull fma2(ull a, ull b, ull c) {
    ull d; asm("fma.rn.f32x2 %0, %1, %2, %3;" : "=l"(d) : "l"(a), "l"(b), "l"(c));
    return d;
}
__device__ __forceinline__ ull d2l(double v) { return __double_as_longlong(v); }

// ---------------- Kernel A: tiny alignment dummy (1st launch) ----------------
__global__ void dummy_kernel() {
    if (threadIdx.x < 32) g_dummy[threadIdx.x] = (int)threadIdx.x;
}

// ---------------- Kernel 0: M = W_main @ W_ref^T ----------------
__global__ void __launch_bounds__(128) wprod_kernel(const float* __restrict__ Wm,
                                                    const float* __restrict__ Wr) {
    __shared__ float wm[128];
    const int c = blockIdx.x;
    const int t = threadIdx.x;
    wm[t] = Wm[c * 128 + t];
    __syncthreads();
    const float4* wr = (const float4*)(Wr + t * 128);
    float s0 = 0.f, s1 = 0.f, s2 = 0.f, s3 = 0.f;
#pragma unroll
    for (int d = 0; d < 32; d += 4) {
        float4 v0 = wr[d + 0], v1 = wr[d + 1], v2 = wr[d + 2], v3 = wr[d + 3];
        s0 += wm[4*d+ 0]*v0.x + wm[4*d+ 1]*v0.y + wm[4*d+ 2]*v0.z + wm[4*d+ 3]*v0.w;
        s1 += wm[4*d+ 4]*v1.x + wm[4*d+ 5]*v1.y + wm[4*d+ 6]*v1.z + wm[4*d+ 7]*v1.w;
        s2 += wm[4*d+ 8]*v2.x + wm[4*d+ 9]*v2.y + wm[4*d+10]*v2.z + wm[4*d+11]*v2.w;
        s3 += wm[4*d+12]*v3.x + wm[4*d+13]*v3.y + wm[4*d+14]*v3.z + wm[4*d+15]*v3.w;
    }
    g_M[c * 128 + t] = (s0 + s1) + (s2 + s3);
}

// ---------------- Kernel 1: A = main @ M, FFMA2, double-buffered ----------------
__global__ void __launch_bounds__(256) gemm_kernel(const float* __restrict__ X) {
    __shared__ float Xs[2][16][128];   // transposed: Xs[buf][k][row]
    __shared__ float Ms[2][16][128];   // Ms[buf][k][col]
    const int tid = threadIdx.x;
    const int tx = tid & 15;
    const int ty = tid >> 4;
    const int row0 = blockIdx.x * 128;

    ull acc[4][8];
#pragma unroll
    for (int p = 0; p < 4; p++)
#pragma unroll
        for (int j = 0; j < 8; j++) acc[p][j] = 0ull;

    const int lr = tid >> 2;            // 0..63
    const int lk = (tid & 3) * 4;       // 0,4,8,12
    const int mr = tid >> 5;            // 0..7
    const int mc = (tid & 31) * 4;      // 0..124

    // prologue: load tile 0 into buffer 0
    {
        float4 xa = *(const float4*)&X[(row0 + lr) * 128 + lk];
        float4 xb = *(const float4*)&X[(row0 + lr + 64) * 128 + lk];
        Xs[0][lk + 0][lr] = xa.x; Xs[0][lk + 1][lr] = xa.y;
        Xs[0][lk + 2][lr] = xa.z; Xs[0][lk + 3][lr] = xa.w;
        Xs[0][lk + 0][lr + 64] = xb.x; Xs[0][lk + 1][lr + 64] = xb.y;
        Xs[0][lk + 2][lr + 64] = xb.z; Xs[0][lk + 3][lr + 64] = xb.w;
        *(float4*)&Ms[0][mr][mc]     = *(const float4*)&g_M[mr * 128 + mc];
        *(float4*)&Ms[0][mr + 8][mc] = *(const float4*)&g_M[(mr + 8) * 128 + mc];
    }
    __syncthreads();

#pragma unroll
    for (int it = 0; it < 8; it++) {
        const int cur = it & 1;
        const int nxt = cur ^ 1;
        float4 nxa, nxb, nma, nmb;
        if (it < 7) {
            const int k1 = (it + 1) * 16;
            nxa = *(const float4*)&X[(row0 + lr) * 128 + k1 + lk];
            nxb = *(const float4*)&X[(row0 + lr + 64) * 128 + k1 + lk];
            nma = *(const float4*)&g_M[(k1 + mr) * 128 + mc];
            nmb = *(const float4*)&g_M[(k1 + mr + 8) * 128 + mc];
        }
#pragma unroll
        for (int k = 0; k < 16; k++) {
            double2 a0 = *(const double2*)&Xs[cur][k][ty * 4];
            double2 a1 = *(const double2*)&Xs[cur][k][64 + ty * 4];
            float4 b0 = *(const float4*)&Ms[cur][k][tx * 4];
            float4 b1 = *(const float4*)&Ms[cur][k][64 + tx * 4];
            ull ap[4] = {d2l(a0.x), d2l(a0.y), d2l(a1.x), d2l(a1.y)};
            ull bp[8] = {pk2(b0.x, b0.x), pk2(b0.y, b0.y), pk2(b0.z, b0.z), pk2(b0.w, b0.w),
                         pk2(b1.x, b1.x), pk2(b1.y, b1.y), pk2(b1.z, b1.z), pk2(b1.w, b1.w)};
#pragma unroll
            for (int p = 0; p < 4; p++)
#pragma unroll
                for (int j = 0; j < 8; j++) acc[p][j] = fma2(ap[p], bp[j], acc[p][j]);
        }
        if (it < 7) {
            Xs[nxt][lk + 0][lr] = nxa.x; Xs[nxt][lk + 1][lr] = nxa.y;
            Xs[nxt][lk + 2][lr] = nxa.z; Xs[nxt][lk + 3][lr] = nxa.w;
            Xs[nxt][lk + 0][lr + 64] = nxb.x; Xs[nxt][lk + 1][lr + 64] = nxb.y;
            Xs[nxt][lk + 2][lr + 64] = nxb.z; Xs[nxt][lk + 3][lr + 64] = nxb.w;
            *(float4*)&Ms[nxt][mr][mc]     = nma;
            *(float4*)&Ms[nxt][mr + 8][mc] = nmb;
            __syncthreads();
        }
    }

    const int rbase[4] = {ty * 4, ty * 4 + 2, 64 + ty * 4, 64 + ty * 4 + 2};
#pragma unroll
    for (int p = 0; p < 4; p++) {
        float lo[8], hi[8];
#pragma unroll
        for (int j = 0; j < 8; j++) upk2(acc[p][j], lo[j], hi[j]);
        const int r0 = row0 + rbase[p];
        *(float4*)&g_A[r0 * 128 + tx * 4]            = make_float4(lo[0], lo[1], lo[2], lo[3]);
        *(float4*)&g_A[r0 * 128 + 64 + tx * 4]       = make_float4(lo[4], lo[5], lo[6], lo[7]);
        *(float4*)&g_A[(r0 + 1) * 128 + tx * 4]      = make_float4(hi[0], hi[1], hi[2], hi[3]);
        *(float4*)&g_A[(r0 + 1) * 128 + 64 + tx * 4] = make_float4(hi[4], hi[5], hi[6], hi[7]);
    }
}

// ---------------- Kernel 2: local 5x5 attention, occ-2, XOR-swizzled smem ----------
#define SREF_W 128
#define SV_W   64
#define SMEM_FLOATS (144 * SREF_W + 144 * SV_W)   // 110592 B

__global__ void __launch_bounds__(256, 2) attn_kernel(const float* __restrict__ ref,
                                                      const float* __restrict__ refv,
                                                      float* __restrict__ out) {
    extern __shared__ float smem[];
    float* sRef = smem;                    // 144 * 128
    float* sV   = sRef + 144 * SREF_W;     // 144 * 64

    const int b = blockIdx.z;
    const int ty0 = blockIdx.y * 8;
    const int tx0 = blockIdx.x * 8;
    const int tid = threadIdx.x;

    const int pixel = tid >> 2;
    const int part  = tid & 3;
    const int py = pixel >> 3;
    const int px = pixel & 7;

    // ---- Q: straight from g_A into packed registers ----
    ull q[16];
    {
        const float4* qp = (const float4*)&g_A[(((b * 128 + ty0 + py) * 128) + tx0 + px) * 128 + part * 32];
#pragma unroll
        for (int m = 0; m < 8; m++) {
            float4 v = qp[m];
            q[2 * m]     = pk2(v.x, v.y);
            q[2 * m + 1] = pk2(v.z, v.w);
        }
    }

    // ---- load ref halo (zero padded), swizzled ----
    for (int t = tid; t < 144 * 32; t += 256) {
        int hp = t >> 5, g = t & 31;
        int gy = ty0 - 2 + hp / 12;
        int gx = tx0 - 2 + hp % 12;
        float4 v = make_float4(0.f, 0.f, 0.f, 0.f);
        if ((unsigned)gy < 128u && (unsigned)gx < 128u)
            v = *(const float4*)&ref[(((b * 128 + gy) * 128) + gx) * 128 + (g << 2)];
        int gp = g ^ (((g >> 3) << 1) & 6) ^ (hp & 1);
        *(float4*)&sRef[hp * SREF_W + (gp << 2)] = v;
    }
    // ---- load value halo (zero padded), swizzled ----
    for (int t = tid; t < 144 * 16; t += 256) {
        int hp = t >> 4, g = t & 15;
        int gy = ty0 - 2 + hp / 12;
        int gx = tx0 - 2 + hp % 12;
        float4 v = make_float4(0.f, 0.f, 0.f, 0.f);
        if ((unsigned)gy < 128u && (unsigned)gx < 128u)
            v = *(const float4*)&refv[(((b * 128 + gy) * 128) + gx) * 64 + (g << 2)];
        int gp = g ^ ((g >> 3) & 1) ^ ((hp & 1) << 1);
        *(float4*)&sV[hp * SV_W + (gp << 2)] = v;
    }
    __syncthreads();

    // ---- logits ----
    ull acc2[25];
#pragma unroll
    for (int n = 0; n < 25; n++) acc2[n] = 0ull;

    const int rowbase = py * 12 + px;
    const int p8 = part << 3;
    const int p2 = part << 1;

#pragma unroll
    for (int dy = 0; dy < 5; dy++)
#pragma unroll
        for (int dx = 0; dx < 5; dx++) {
            const int n = dy * 5 + dx;
            const int row = rowbase + dy * 12 + dx;
            const int c = p2 ^ (row & 1);
            const float* kr = &sRef[row * SREF_W];
            ull a = acc2[n];
#pragma unroll
            for (int m = 0; m < 8; m++) {
                float4 kv = *(const float4*)&kr[(p8 + (m ^ c)) << 2];
                a = fma2(q[2 * m],     pk2(kv.x, kv.y), a);
                a = fma2(q[2 * m + 1], pk2(kv.z, kv.w), a);
            }
            acc2[n] = a;
        }

    float logit[25];
#pragma unroll
    for (int n = 0; n < 25; n++) {
        float lo, hi; upk2(acc2[n], lo, hi);
        float v = lo + hi;
        v += __shfl_xor_sync(0xffffffffu, v, 1);
        v += __shfl_xor_sync(0xffffffffu, v, 2);
        logit[n] = v;
    }

    float mx = logit[0];
#pragma unroll
    for (int n = 1; n < 25; n++) mx = fmaxf(mx, logit[n]);
    float s = 0.f;
#pragma unroll
    for (int n = 0; n < 25; n++) { logit[n] = __expf(logit[n] - mx); s += logit[n]; }
    const float inv = 1.f / s;

    ull o2[8];
#pragma unroll
    for (int i = 0; i < 8; i++) o2[i] = 0ull;
    const int vp4 = part << 2;
    const int vc0 = part >> 1;
#pragma unroll
    for (int dy = 0; dy < 5; dy++)
#pragma unroll
        for (int dx = 0; dx < 5; dx++) {
            const int n = dy * 5 + dx;
            const int row = rowbase + dy * 12 + dx;
            const int c = vc0 ^ ((row & 1) << 1);
            const float* vr = &sV[row * SV_W];
            const ull w2 = pk2(logit[n], logit[n]);
#pragma unroll
            for (int m = 0; m < 4; m++) {
                float4 v = *(const float4*)&vr[(vp4 + (m ^ c)) << 2];
                o2[2 * m]     = fma2(w2, pk2(v.x, v.y), o2[2 * m]);
                o2[2 * m + 1] = fma2(w2, pk2(v.z, v.w), o2[2 * m + 1]);
            }
        }

    const int gy = ty0 + py;
    const int gx = tx0 + px;
    float* op = &out[(((b * 128 + gy) * 128) + gx) * 64 + part * 16];
#pragma unroll
    for (int i = 0; i < 4; i++) {
        float a0, a1, a2, a3;
        upk2(o2[2 * i], a0, a1);
        upk2(o2[2 * i + 1], a2, a3);
        *(float4*)&op[4 * i] = make_float4(a0 * inv, a1 * inv, a2 * inv, a3 * inv);
    }
}

// ---------------- launch ----------------
extern "C" void kernel_launch(void* const* d_in, const int* in_sizes, int n_in,
                              void* d_out, int out_size) {
    const float* main_ = (const float*)d_in[0];
    const float* ref   = (const float*)d_in[1];
    const float* refv  = (const float*)d_in[2];
    const float* Wm    = (const float*)d_in[3];
    const float* Wr    = (const float*)d_in[4];
    float* out = (float*)d_out;

    const size_t smem_bytes = SMEM_FLOATS * sizeof(float);  // 110592
    cudaFuncSetAttribute(attn_kernel, cudaFuncAttributeMaxDynamicSharedMemorySize,
                         (int)smem_bytes);

    // position-4 launch gets profiled by ncu -> attn_kernel
    dummy_kernel<<<1, 32>>>();
    wprod_kernel<<<128, 128>>>(Wm, Wr);
    gemm_kernel<<<512, 256>>>(main_);
    attn_kernel<<<dim3(16, 16, 4), 256, smem_bytes>>>(ref, refv, out);
}

// round 12
// speedup vs baseline: 1.8479x; 1.2751x over previous
#include <cuda_runtime.h>

typedef unsigned long long ull;

// ---------------- scratch (no cudaMalloc allowed) ----------------
__device__ float g_M[128 * 128];                 // W_main @ W_ref^T
__device__ float g_A[4 * 128 * 128 * 128];       // main @ M
__device__ int   g_dummy[32];

// ---------------- packed fp32x2 helpers ----------------
__device__ __forceinline__ ull pk2(float lo, float hi) {
    ull r; asm("mov.b64 %0, {%1,%2};" : "=l"(r) : "f"(lo), "f"(hi)); return r;
}
__device__ __forceinline__ void upk2(ull v, float& lo, float& hi) {
    asm("mov.b64 {%0,%1}, %2;" : "=f"(lo), "=f"(hi) : "l"(v));
}
__device__ __forceinline__ ull fma2(ull a, ull b, ull c) {
    ull d; asm("fma.rn.f32x2 %0, %1, %2, %3;" : "=l"(d) : "l"(a), "l"(b), "l"(c));
    return d;
}
__device__ __forceinline__ ull d2l(double v) { return __double_as_longlong(v); }

// ---------------- Kernel A: tiny alignment dummy (1st launch) ----------------
__global__ void dummy_kernel() {
    if (threadIdx.x < 32) g_dummy[threadIdx.x] = (int)threadIdx.x;
}

// ---------------- Kernel 0: M = W_main @ W_ref^T ----------------
__global__ void __launch_bounds__(128) wprod_kernel(const float* __restrict__ Wm,
                                                    const float* __restrict__ Wr) {
    __shared__ float wm[128];
    const int c = blockIdx.x;
    const int t = threadIdx.x;
    wm[t] = Wm[c * 128 + t];
    __syncthreads();
    const float4* wr = (const float4*)(Wr + t * 128);
    float s0 = 0.f, s1 = 0.f, s2 = 0.f, s3 = 0.f;
#pragma unroll
    for (int d = 0; d < 32; d += 4) {
        float4 v0 = wr[d + 0], v1 = wr[d + 1], v2 = wr[d + 2], v3 = wr[d + 3];
        s0 += wm[4*d+ 0]*v0.x + wm[4*d+ 1]*v0.y + wm[4*d+ 2]*v0.z + wm[4*d+ 3]*v0.w;
        s1 += wm[4*d+ 4]*v1.x + wm[4*d+ 5]*v1.y + wm[4*d+ 6]*v1.z + wm[4*d+ 7]*v1.w;
        s2 += wm[4*d+ 8]*v2.x + wm[4*d+ 9]*v2.y + wm[4*d+10]*v2.z + wm[4*d+11]*v2.w;
        s3 += wm[4*d+12]*v3.x + wm[4*d+13]*v3.y + wm[4*d+14]*v3.z + wm[4*d+15]*v3.w;
    }
    g_M[c * 128 + t] = (s0 + s1) + (s2 + s3);
}

// ---------------- Kernel 1: A = main @ M, FFMA2, double-buffered ----------------
__global__ void __launch_bounds__(256) gemm_kernel(const float* __restrict__ X) {
    __shared__ float Xs[2][16][128];
    __shared__ float Ms[2][16][128];
    const int tid = threadIdx.x;
    const int tx = tid & 15;
    const int ty = tid >> 4;
    const int row0 = blockIdx.x * 128;

    ull acc[4][8];
#pragma unroll
    for (int p = 0; p < 4; p++)
#pragma unroll
        for (int j = 0; j < 8; j++) acc[p][j] = 0ull;

    const int lr = tid >> 2;
    const int lk = (tid & 3) * 4;
    const int mr = tid >> 5;
    const int mc = (tid & 31) * 4;

    {
        float4 xa = *(const float4*)&X[(row0 + lr) * 128 + lk];
        float4 xb = *(const float4*)&X[(row0 + lr + 64) * 128 + lk];
        Xs[0][lk + 0][lr] = xa.x; Xs[0][lk + 1][lr] = xa.y;
        Xs[0][lk + 2][lr] = xa.z; Xs[0][lk + 3][lr] = xa.w;
        Xs[0][lk + 0][lr + 64] = xb.x; Xs[0][lk + 1][lr + 64] = xb.y;
        Xs[0][lk + 2][lr + 64] = xb.z; Xs[0][lk + 3][lr + 64] = xb.w;
        *(float4*)&Ms[0][mr][mc]     = *(const float4*)&g_M[mr * 128 + mc];
        *(float4*)&Ms[0][mr + 8][mc] = *(const float4*)&g_M[(mr + 8) * 128 + mc];
    }
    __syncthreads();

#pragma unroll
    for (int it = 0; it < 8; it++) {
        const int cur = it & 1;
        const int nxt = cur ^ 1;
        float4 nxa, nxb, nma, nmb;
        if (it < 7) {
            const int k1 = (it + 1) * 16;
            nxa = *(const float4*)&X[(row0 + lr) * 128 + k1 + lk];
            nxb = *(const float4*)&X[(row0 + lr + 64) * 128 + k1 + lk];
            nma = *(const float4*)&g_M[(k1 + mr) * 128 + mc];
            nmb = *(const float4*)&g_M[(k1 + mr + 8) * 128 + mc];
        }
#pragma unroll
        for (int k = 0; k < 16; k++) {
            double2 a0 = *(const double2*)&Xs[cur][k][ty * 4];
            double2 a1 = *(const double2*)&Xs[cur][k][64 + ty * 4];
            float4 b0 = *(const float4*)&Ms[cur][k][tx * 4];
            float4 b1 = *(const float4*)&Ms[cur][k][64 + tx * 4];
            ull ap[4] = {d2l(a0.x), d2l(a0.y), d2l(a1.x), d2l(a1.y)};
            ull bp[8] = {pk2(b0.x, b0.x), pk2(b0.y, b0.y), pk2(b0.z, b0.z), pk2(b0.w, b0.w),
                         pk2(b1.x, b1.x), pk2(b1.y, b1.y), pk2(b1.z, b1.z), pk2(b1.w, b1.w)};
#pragma unroll
            for (int p = 0; p < 4; p++)
#pragma unroll
                for (int j = 0; j < 8; j++) acc[p][j] = fma2(ap[p], bp[j], acc[p][j]);
        }
        if (it < 7) {
            Xs[nxt][lk + 0][lr] = nxa.x; Xs[nxt][lk + 1][lr] = nxa.y;
            Xs[nxt][lk + 2][lr] = nxa.z; Xs[nxt][lk + 3][lr] = nxa.w;
            Xs[nxt][lk + 0][lr + 64] = nxb.x; Xs[nxt][lk + 1][lr + 64] = nxb.y;
            Xs[nxt][lk + 2][lr + 64] = nxb.z; Xs[nxt][lk + 3][lr + 64] = nxb.w;
            *(float4*)&Ms[nxt][mr][mc]     = nma;
            *(float4*)&Ms[nxt][mr + 8][mc] = nmb;
            __syncthreads();
        }
    }

    const int rbase[4] = {ty * 4, ty * 4 + 2, 64 + ty * 4, 64 + ty * 4 + 2};
#pragma unroll
    for (int p = 0; p < 4; p++) {
        float lo[8], hi[8];
#pragma unroll
        for (int j = 0; j < 8; j++) upk2(acc[p][j], lo[j], hi[j]);
        const int r0 = row0 + rbase[p];
        *(float4*)&g_A[r0 * 128 + tx * 4]            = make_float4(lo[0], lo[1], lo[2], lo[3]);
        *(float4*)&g_A[r0 * 128 + 64 + tx * 4]       = make_float4(lo[4], lo[5], lo[6], lo[7]);
        *(float4*)&g_A[(r0 + 1) * 128 + tx * 4]      = make_float4(hi[0], hi[1], hi[2], hi[3]);
        *(float4*)&g_A[(r0 + 1) * 128 + 64 + tx * 4] = make_float4(hi[4], hi[5], hi[6], hi[7]);
    }
}

// ---------------- Kernel 2: local 5x5 attention, ILP-restructured ----------
// Same XOR-swizzled layouts as R3; inner loops are now pure LDS.128+FFMA2
// with parity-split precomputed base pointers (all row offsets are immediates).
#define SREF_W 128
#define SV_W   64
#define SMEM_FLOATS (144 * SREF_W + 144 * SV_W)   // 110592 B

__global__ void __launch_bounds__(256, 2) attn_kernel(const float* __restrict__ ref,
                                                      const float* __restrict__ refv,
                                                      float* __restrict__ out) {
    extern __shared__ float smem[];
    float* sRef = smem;                    // 144 * 128
    float* sV   = sRef + 144 * SREF_W;     // 144 * 64

    const int b = blockIdx.z;
    const int ty0 = blockIdx.y * 8;
    const int tx0 = blockIdx.x * 8;
    const int tid = threadIdx.x;

    const int pixel = tid >> 2;
    const int part  = tid & 3;
    const int py = pixel >> 3;
    const int px = pixel & 7;

    // ---- Q: straight from g_A into packed registers ----
    ull q[16];
    {
        const float4* qp = (const float4*)&g_A[(((b * 128 + ty0 + py) * 128) + tx0 + px) * 128 + part * 32];
#pragma unroll
        for (int m = 0; m < 8; m++) {
            float4 v = qp[m];
            q[2 * m]     = pk2(v.x, v.y);
            q[2 * m + 1] = pk2(v.z, v.w);
        }
    }

    // ---- load ref halo (zero padded), swizzled; g invariant, y via mul-shift ----
    {
        const int g = tid & 31;
        const int gsw = g ^ (((g >> 3) << 1) & 6);
#pragma unroll
        for (int it = 0; it < 18; it++) {
            const int hp = (tid >> 5) + it * 8;
            const int hy = (hp * 171) >> 11;      // hp / 12 for hp in [0,144)
            const int hx = hp - hy * 12;
            const int gy = ty0 - 2 + hy;
            const int gx = tx0 - 2 + hx;
            float4 v = make_float4(0.f, 0.f, 0.f, 0.f);
            if ((unsigned)gy < 128u && (unsigned)gx < 128u)
                v = *(const float4*)&ref[(((b * 128 + gy) * 128) + gx) * 128 + (g << 2)];
            *(float4*)&sRef[hp * SREF_W + ((gsw ^ (hp & 1)) << 2)] = v;
        }
    }
    // ---- load value halo (zero padded), swizzled ----
    {
        const int g = tid & 15;
        const int gsw = g ^ ((g >> 3) & 1);
#pragma unroll
        for (int it = 0; it < 9; it++) {
            const int hp = (tid >> 4) + it * 16;
            const int hy = (hp * 171) >> 11;
            const int hx = hp - hy * 12;
            const int gy = ty0 - 2 + hy;
            const int gx = tx0 - 2 + hx;
            float4 v = make_float4(0.f, 0.f, 0.f, 0.f);
            if ((unsigned)gy < 128u && (unsigned)gx < 128u)
                v = *(const float4*)&refv[(((b * 128 + gy) * 128) + gx) * 64 + (g << 2)];
            *(float4*)&sV[hp * SV_W + ((gsw ^ ((hp & 1) << 1)) << 2)] = v;
        }
    }
    __syncthreads();

    const int rowbase = py * 12 + px;
    const int rp = rowbase & 1;
    const int p8 = part << 3;
    const int p2 = part << 1;

    // ---- logits: m-outer / n-inner, parity-split bases, imm row offsets ----
    ull acc2[25];
#pragma unroll
    for (int n = 0; n < 25; n++) acc2[n] = 0ull;

    {
        const float* kb = &sRef[rowbase * SREF_W];
        const int cbase = p2 ^ rp;
#pragma unroll
        for (int m = 0; m < 8; m++) {
            const ull q0 = q[2 * m], q1 = q[2 * m + 1];
            const float* be = kb + ((p8 + (m ^ cbase)) << 2);
            const float* bo = kb + ((p8 + (m ^ cbase ^ 1)) << 2);
#pragma unroll
            for (int dy = 0; dy < 5; dy++)
#pragma unroll
                for (int dx = 0; dx < 5; dx++) {
                    const int D = dy * 12 + dx;
                    const int n = dy * 5 + dx;
                    const float* p = (((D & 1) == 0) ? be : bo) + D * SREF_W;
                    float4 kv = *(const float4*)p;
                    acc2[n] = fma2(q0, pk2(kv.x, kv.y), acc2[n]);
                    acc2[n] = fma2(q1, pk2(kv.z, kv.w), acc2[n]);
                }
        }
    }

    // horizontal: pair-sum, then reduce the 4 channel-parts via shfl
    float logit[25];
#pragma unroll
    for (int n = 0; n < 25; n++) {
        float lo, hi; upk2(acc2[n], lo, hi);
        float v = lo + hi;
        v += __shfl_xor_sync(0xffffffffu, v, 1);
        v += __shfl_xor_sync(0xffffffffu, v, 2);
        logit[n] = v;
    }

    // softmax over 25 (redundant in the 4 part-lanes)
    float mx = logit[0];
#pragma unroll
    for (int n = 1; n < 25; n++) mx = fmaxf(mx, logit[n]);
    float s = 0.f;
#pragma unroll
    for (int n = 0; n < 25; n++) { logit[n] = __expf(logit[n] - mx); s += logit[n]; }
    const float inv = 1.f / s;

    // ---- weighted value sum: 8 parity-split precomputed bases, imm offsets ----
    ull o2[8];
#pragma unroll
    for (int i = 0; i < 8; i++) o2[i] = 0ull;
    {
        const float* vb = &sV[rowbase * SV_W];
        const int vp4 = part << 2;
        const int c_e = (part >> 1) ^ (rp << 1);
        const int c_o = c_e ^ 2;
        const float* vbe[4];
        const float* vbo[4];
#pragma unroll
        for (int m = 0; m < 4; m++) {
            vbe[m] = vb + ((vp4 + (m ^ c_e)) << 2);
            vbo[m] = vb + ((vp4 + (m ^ c_o)) << 2);
        }
#pragma unroll
        for (int dy = 0; dy < 5; dy++)
#pragma unroll
            for (int dx = 0; dx < 5; dx++) {
                const int D = dy * 12 + dx;
                const int n = dy * 5 + dx;
                const ull w2 = pk2(logit[n], logit[n]);
#pragma unroll
                for (int m = 0; m < 4; m++) {
                    const float* p = (((D & 1) == 0) ? vbe[m] : vbo[m]) + D * SV_W;
                    float4 v = *(const float4*)p;
                    o2[2 * m]     = fma2(w2, pk2(v.x, v.y), o2[2 * m]);
                    o2[2 * m + 1] = fma2(w2, pk2(v.z, v.w), o2[2 * m + 1]);
                }
            }
    }

    const int gy = ty0 + py;
    const int gx = tx0 + px;
    float* op = &out[(((b * 128 + gy) * 128) + gx) * 64 + part * 16];
#pragma unroll
    for (int i = 0; i < 4; i++) {
        float a0, a1, a2, a3;
        upk2(o2[2 * i], a0, a1);
        upk2(o2[2 * i + 1], a2, a3);
        *(float4*)&op[4 * i] = make_float4(a0 * inv, a1 * inv, a2 * inv, a3 * inv);
    }
}

// ---------------- launch ----------------
extern "C" void kernel_launch(void* const* d_in, const int* in_sizes, int n_in,
                              void* d_out, int out_size) {
    const float* main_ = (const float*)d_in[0];
    const float* ref   = (const float*)d_in[1];
    const float* refv  = (const float*)d_in[2];
    const float* Wm    = (const float*)d_in[3];
    const float* Wr    = (const float*)d_in[4];
    float* out = (float*)d_out;

    const size_t smem_bytes = SMEM_FLOATS * sizeof(float);  // 110592
    cudaFuncSetAttribute(attn_kernel, cudaFuncAttributeMaxDynamicSharedMemorySize,
                         (int)smem_bytes);

    // position-4 launch gets profiled by ncu -> attn_kernel
    dummy_kernel<<<1, 32>>>();
    wprod_kernel<<<128, 128>>>(Wm, Wr);
    gemm_kernel<<<512, 256>>>(main_);
    attn_kernel<<<dim3(16, 16, 4), 256, smem_bytes>>>(ref, refv, out);
}